// round 12
// baseline (speedup 1.0000x reference)
#include <cuda_runtime.h>
#include <cuda_fp16.h>
#include <cstdint>

#define NBATCH 2
#define LSEQ   2048
#define EMB    1024
#define NHEAD  16
#define HD     64
#define ODIM   1024

__device__ __half g_Qp[NBATCH * LSEQ * EMB];
__device__ __half g_Kp[NBATCH * LSEQ * EMB];
__device__ __half g_Vp[NBATCH * LSEQ * EMB];
__device__ __half g_AOh[NBATCH * LSEQ * EMB];
__device__ __half g_Wh[ODIM * EMB];

__device__ __forceinline__ uint32_t smem_u32(const void* p) {
    uint32_t a;
    asm("{ .reg .u64 t; cvta.to.shared.u64 t, %1; cvt.u32.u64 %0, t; }"
        : "=r"(a) : "l"(p));
    return a;
}
__device__ __forceinline__ void mma16(float* c, const uint32_t* a,
                                      uint32_t b0, uint32_t b1) {
    asm volatile(
        "mma.sync.aligned.m16n8k16.row.col.f32.f16.f16.f32 "
        "{%0,%1,%2,%3}, {%4,%5,%6,%7}, {%8,%9}, {%0,%1,%2,%3};"
        : "+f"(c[0]), "+f"(c[1]), "+f"(c[2]), "+f"(c[3])
        : "r"(a[0]), "r"(a[1]), "r"(a[2]), "r"(a[3]), "r"(b0), "r"(b1));
}
#define LDSM4(r0, r1, r2, r3, addr) \
    asm volatile("ldmatrix.sync.aligned.m8n8.x4.shared.b16 {%0,%1,%2,%3}, [%4];" \
                 : "=r"(r0), "=r"(r1), "=r"(r2), "=r"(r3) : "r"(addr))
#define LDSM4T(r0, r1, r2, r3, addr) \
    asm volatile("ldmatrix.sync.aligned.m8n8.x4.trans.shared.b16 {%0,%1,%2,%3}, [%4];" \
                 : "=r"(r0), "=r"(r1), "=r"(r2), "=r"(r3) : "r"(addr))
#define CPA16(sm, gp) \
    asm volatile("cp.async.cg.shared.global [%0], [%1], 16;" :: "r"(sm), "l"(gp))
#define CPA_COMMIT() asm volatile("cp.async.commit_group;")
#define CPA_WAIT1()  asm volatile("cp.async.wait_group 1;")
#define CPA_WAIT0()  asm volatile("cp.async.wait_group 0;")

// exp(s/32) via exp2 bit trick + degree-5 poly, FMA pipe only (rel err ~2e-6)
__device__ __forceinline__ float fexp32(float s) {
    float y = s * 0.0450842200f;                 // (1/32)*log2(e)
    float z = y + 12582912.0f;
    int   e = __float_as_int(z) << 23;
    float f = y - (z - 12582912.0f);
    float r = 1.3333558e-3f;
    r = fmaf(r, f, 9.6181291e-3f);
    r = fmaf(r, f, 5.5504109e-2f);
    r = fmaf(r, f, 2.4022651e-1f);
    r = fmaf(r, f, 6.9314718e-1f);
    r = fmaf(r, f, 1.0f);
    return r * __int_as_float(e + 0x3f800000);
}

// =============== Wout -> f16 ===============================================
__global__ __launch_bounds__(256) void convw_kernel(
    const float* __restrict__ W, __half* __restrict__ Wh)
{
    int i = (blockIdx.x * 256 + threadIdx.x) * 4;
    float4 v = *(const float4*)(W + i);
    __half2 a = __floats2half2_rn(v.x, v.y);
    __half2 b = __floats2half2_rn(v.z, v.w);
    *(uint2*)(Wh + i) = make_uint2(*(uint32_t*)&a, *(uint32_t*)&b);
}

// ============== fused per-head projections (HMMA) ==========================
__global__ __launch_bounds__(256) void proj3_mma(
    const float* __restrict__ Xv, const float* __restrict__ Wv, __half* __restrict__ Yv,
    const float* __restrict__ Xk, const float* __restrict__ Wk, __half* __restrict__ Yk,
    const float* __restrict__ Xq, const float* __restrict__ Wq, __half* __restrict__ Yq)
{
    const float* X; const float* W; __half* Y;
    if (blockIdx.y == 0)      { X = Xv; W = Wv; Y = Yv; }
    else if (blockIdx.y == 1) { X = Xk; W = Wk; Y = Yk; }
    else                      { X = Xq; W = Wq; Y = Yq; }

    __shared__ __half Xs[128 * 64];
    __shared__ __half Ws[64 * 64];
    const int t = threadIdx.x, lane = t & 31, w = t >> 5;
    const int rb = blockIdx.x << 7;
    const uint32_t xsb = smem_u32(Xs), wsb = smem_u32(Ws);

#pragma unroll
    for (int p = 0; p < 4; ++p) {
        int idx = p * 256 + t, row = idx >> 3, ch = idx & 7;
        uint32_t so = (uint32_t)(row * 128 + ((ch ^ (row & 7)) << 4));
        size_t g = (size_t)(rb + row) * 64 + ch * 8;
        float4 a = *(const float4*)(X + g);
        float4 b = *(const float4*)(X + g + 4);
        __half2 h0 = __floats2half2_rn(a.x, a.y), h1 = __floats2half2_rn(a.z, a.w);
        __half2 h2 = __floats2half2_rn(b.x, b.y), h3 = __floats2half2_rn(b.z, b.w);
        *(uint4*)((char*)Xs + so) = make_uint4(*(uint32_t*)&h0, *(uint32_t*)&h1,
                                               *(uint32_t*)&h2, *(uint32_t*)&h3);
    }
#pragma unroll
    for (int p = 0; p < 2; ++p) {
        int idx = p * 256 + t, row = idx >> 3, ch = idx & 7;
        uint32_t so = (uint32_t)(row * 128 + ((ch ^ (row & 7)) << 4));
        size_t g = (size_t)row * 64 + ch * 8;
        float4 a = *(const float4*)(W + g);
        float4 b = *(const float4*)(W + g + 4);
        __half2 h0 = __floats2half2_rn(a.x, a.y), h1 = __floats2half2_rn(a.z, a.w);
        __half2 h2 = __floats2half2_rn(b.x, b.y), h3 = __floats2half2_rn(b.z, b.w);
        *(uint4*)((char*)Ws + so) = make_uint4(*(uint32_t*)&h0, *(uint32_t*)&h1,
                                               *(uint32_t*)&h2, *(uint32_t*)&h3);
    }
    __syncthreads();

    const int r0 = w * 16;
    float acc[8][4] = {};
#pragma unroll
    for (int kc = 0; kc < 4; ++kc) {
        int arow = r0 + ((lane >> 3) & 1) * 8 + (lane & 7);
        int ach  = kc * 2 + (lane >> 4);
        uint32_t aoff = (uint32_t)(arow * 128 + ((ach ^ (arow & 7)) << 4));
        uint32_t a[4];
        LDSM4(a[0], a[1], a[2], a[3], xsb + aoff);
#pragma unroll
        for (int jt2 = 0; jt2 < 4; ++jt2) {
            int wrow = jt2 * 16 + (lane >> 4) * 8 + (lane & 7);
            int wch  = kc * 2 + ((lane >> 3) & 1);
            uint32_t woff = (uint32_t)(wrow * 128 + ((wch ^ (wrow & 7)) << 4));
            uint32_t b0, b1, b2, b3;
            LDSM4(b0, b1, b2, b3, wsb + woff);
            mma16(acc[2 * jt2 + 0], a, b0, b1);
            mma16(acc[2 * jt2 + 1], a, b2, b3);
        }
    }

    const int g = lane >> 2, tq = lane & 3;
    __half* rowA = Y + (size_t)(rb + r0 + g) * 64;
    __half* rowB = Y + (size_t)(rb + r0 + g + 8) * 64;
#pragma unroll
    for (int dt = 0; dt < 8; ++dt) {
        int col = dt * 8 + tq * 2;
        *(__half2*)(rowA + col) = __floats2half2_rn(acc[dt][0], acc[dt][1]);
        *(__half2*)(rowB + col) = __floats2half2_rn(acc[dt][2], acc[dt][3]);
    }
}

// ======================= flash attention (HMMA + cp.async) =================
#define QSTR 72
#define FKOFF 18432                    // Qs: 128*72*2 bytes
#define FVOFF (FKOFF + 2 * 9216)      // Ks: 2 stages * 64*72*2
#define FSMEM (FVOFF + 2 * 9216)      // 55296 bytes
__global__ __launch_bounds__(256) void flash_mma(
    const __half* __restrict__ Qp, const __half* __restrict__ Kp,
    const __half* __restrict__ Vp, __half* __restrict__ AOh)
{
    extern __shared__ char smb[];
    __half* Qs = (__half*)smb;
    const int t = threadIdx.x, lane = t & 31, w = t >> 5;
    const int nh = blockIdx.y;
    const int qb = blockIdx.x << 7;
    const size_t base = ((size_t)(nh >> 4) * LSEQ * NHEAD + (size_t)(nh & 15)) * HD;
    const uint32_t sbase = smem_u32(smb);
    const uint32_t ksb = sbase + FKOFF, vsb = sbase + FVOFF;
    const int lrow = t >> 3, lc8 = (t & 7) * 8;

    {   // prologue: issue K/V stage 0
        const size_t g0 = base + (size_t)(lrow) * (NHEAD * HD) + lc8;
        const size_t g1 = base + (size_t)(lrow + 32) * (NHEAD * HD) + lc8;
        uint32_t s0 = (uint32_t)((lrow * QSTR + lc8) * 2);
        uint32_t s1 = (uint32_t)(((lrow + 32) * QSTR + lc8) * 2);
        CPA16(ksb + s0, Kp + g0); CPA16(ksb + s1, Kp + g1);
        CPA16(vsb + s0, Vp + g0); CPA16(vsb + s1, Vp + g1);
        CPA_COMMIT();
    }
#pragma unroll
    for (int p = 0; p < 4; ++p) {
        int row = p * 32 + lrow;
        *(uint4*)(Qs + row * QSTR + lc8) =
            *(const uint4*)(Qp + base + (size_t)(qb + row) * (NHEAD * HD) + lc8);
    }
    __syncthreads();

    const int r0 = w * 16;
    uint32_t qa[4][4];
#pragma unroll
    for (int kc = 0; kc < 4; ++kc) {
        uint32_t addr = sbase + (uint32_t)((r0 + ((lane >> 3) & 1) * 8 + (lane & 7)) * (QSTR * 2)
                                           + kc * 32 + (lane >> 4) * 16);
        LDSM4(qa[kc][0], qa[kc][1], qa[kc][2], qa[kc][3], addr);
    }

    float oacc[8][4] = {};
    float lacc[4] = {};
    const uint32_t ONES = 0x3C003C00u;   // half2(1.0, 1.0)

    for (int kb = 0; kb < LSEQ / 64; ++kb) {
        const uint32_t st = (uint32_t)(kb & 1) * 9216;
        if (kb < LSEQ / 64 - 1) {
            const uint32_t sn = (uint32_t)((kb + 1) & 1) * 9216;
            const size_t g0 = base + (size_t)((kb + 1) * 64 + lrow) * (NHEAD * HD) + lc8;
            const size_t g1 = base + (size_t)((kb + 1) * 64 + lrow + 32) * (NHEAD * HD) + lc8;
            uint32_t s0 = sn + (uint32_t)((lrow * QSTR + lc8) * 2);
            uint32_t s1 = sn + (uint32_t)(((lrow + 32) * QSTR + lc8) * 2);
            CPA16(ksb + s0, Kp + g0); CPA16(ksb + s1, Kp + g1);
            CPA16(vsb + s0, Vp + g0); CPA16(vsb + s1, Vp + g1);
            CPA_COMMIT();
            CPA_WAIT1();
        } else {
            CPA_WAIT0();
        }
        __syncthreads();

        float sacc[8][4] = {};
#pragma unroll
        for (int kc = 0; kc < 4; ++kc) {
#pragma unroll
            for (int jt2 = 0; jt2 < 4; ++jt2) {
                uint32_t b0, b1, b2, b3;
                uint32_t addr = ksb + st + (uint32_t)((jt2 * 16 + (lane >> 4) * 8 + (lane & 7)) * (QSTR * 2)
                                                      + kc * 32 + ((lane >> 3) & 1) * 16);
                LDSM4(b0, b1, b2, b3, addr);
                mma16(sacc[2 * jt2 + 0], qa[kc], b0, b1);
                mma16(sacc[2 * jt2 + 1], qa[kc], b2, b3);
            }
        }

        uint32_t pa[4][4];
#pragma unroll
        for (int jt = 0; jt < 8; ++jt) {
            float p0 = fexp32(sacc[jt][0]);
            float p1 = fexp32(sacc[jt][1]);
            float p2 = fexp32(sacc[jt][2]);
            float p3 = fexp32(sacc[jt][3]);
            __half2 h01 = __floats2half2_rn(p0, p1);
            __half2 h23 = __floats2half2_rn(p2, p3);
            pa[jt >> 1][(jt & 1) * 2 + 0] = *(uint32_t*)&h01;
            pa[jt >> 1][(jt & 1) * 2 + 1] = *(uint32_t*)&h23;
        }

#pragma unroll
        for (int jc = 0; jc < 4; ++jc) {
            mma16(lacc, pa[jc], ONES, ONES);   // row-sums: lsum += P @ 1
#pragma unroll
            for (int dt2 = 0; dt2 < 4; ++dt2) {
                uint32_t b0, b1, b2, b3;
                uint32_t addr = vsb + st + (uint32_t)((jc * 16 + ((lane >> 3) & 1) * 8 + (lane & 7)) * (QSTR * 2)
                                                      + dt2 * 32 + (lane >> 4) * 16);
                LDSM4T(b0, b1, b2, b3, addr);
                mma16(oacc[2 * dt2 + 0], pa[jc], b0, b1);
                mma16(oacc[2 * dt2 + 1], pa[jc], b2, b3);
            }
        }
        __syncthreads();
    }

    const float inv0 = 1.0f / lacc[0], inv1 = 1.0f / lacc[2];
    const int g = lane >> 2, tq = lane & 3;
    __half* rowA = AOh + base + (size_t)(qb + r0 + g) * (NHEAD * HD);
    __half* rowB = AOh + base + (size_t)(qb + r0 + g + 8) * (NHEAD * HD);
#pragma unroll
    for (int dt = 0; dt < 8; ++dt) {
        int col = dt * 8 + tq * 2;
        *(__half2*)(rowA + col) = __floats2half2_rn(oacc[dt][0] * inv0, oacc[dt][1] * inv0);
        *(__half2*)(rowB + col) = __floats2half2_rn(oacc[dt][2] * inv1, oacc[dt][3] * inv1);
    }
}

// =============== output projection (HMMA f16, 128x128 tiles) ===============
#define OPA 0
#define OPW 16384
#define OPST 32768
#define OPSM (2 * OPST)   // 65536 bytes
__global__ __launch_bounds__(256, 2) void outproj_mma(
    const __half* __restrict__ Ah_g, const __half* __restrict__ Wh_g,
    const float* __restrict__ bias, float* __restrict__ Y)
{
    extern __shared__ char smb[];
    const int t = threadIdx.x, lane = t & 31, w = t >> 5;
    const int ob = blockIdx.x << 7, rb = blockIdx.y << 7;
    const uint32_t sb = smem_u32(smb);
    const int r0 = w * 16;
    float acc[16][4] = {};
    const int lrow = t >> 3, lch = t & 7;

    {   // prologue: stage 0
#pragma unroll
        for (int p = 0; p < 4; ++p) {
            int row = lrow + p * 32;
            uint32_t so = (uint32_t)(row * 128 + ((lch ^ (row & 7)) << 4));
            CPA16(sb + OPA + so, Ah_g + (size_t)(rb + row) * EMB + lch * 8);
            CPA16(sb + OPW + so, Wh_g + (size_t)(ob + row) * EMB + lch * 8);
        }
        CPA_COMMIT();
    }

    for (int ki = 0; ki < EMB / 64; ++ki) {
        const uint32_t st = (uint32_t)(ki & 1) * OPST;
        if (ki < EMB / 64 - 1) {
            const uint32_t sn = (uint32_t)((ki + 1) & 1) * OPST;
            const int kk = (ki + 1) * 64;
#pragma unroll
            for (int p = 0; p < 4; ++p) {
                int row = lrow + p * 32;
                uint32_t so = (uint32_t)(row * 128 + ((lch ^ (row & 7)) << 4));
                CPA16(sb + sn + OPA + so, Ah_g + (size_t)(rb + row) * EMB + kk + lch * 8);
                CPA16(sb + sn + OPW + so, Wh_g + (size_t)(ob + row) * EMB + kk + lch * 8);
            }
            CPA_COMMIT();
            CPA_WAIT1();
        } else {
            CPA_WAIT0();
        }
        __syncthreads();

#pragma unroll
        for (int kc = 0; kc < 4; ++kc) {
            int arow = r0 + ((lane >> 3) & 1) * 8 + (lane & 7);
            int ach  = kc * 2 + (lane >> 4);
            uint32_t aoff = (uint32_t)(arow * 128 + ((ach ^ (arow & 7)) << 4));
            uint32_t a[4];
            LDSM4(a[0], a[1], a[2], a[3], sb + st + OPA + aoff);
#pragma unroll
            for (int jt2 = 0; jt2 < 8; ++jt2) {
                int wrow = jt2 * 16 + (lane >> 4) * 8 + (lane & 7);
                int wch  = kc * 2 + ((lane >> 3) & 1);
                uint32_t woff = (uint32_t)(wrow * 128 + ((wch ^ (wrow & 7)) << 4));
                uint32_t b0, b1, b2, b3;
                LDSM4(b0, b1, b2, b3, sb + st + OPW + woff);
                mma16(acc[2 * jt2 + 0], a, b0, b1);
                mma16(acc[2 * jt2 + 1], a, b2, b3);
            }
        }
        __syncthreads();
    }

    const int g = lane >> 2, tq = lane & 3;
    float* rowA = Y + (size_t)(rb + r0 + g) * ODIM;
    float* rowB = Y + (size_t)(rb + r0 + g + 8) * ODIM;
#pragma unroll
    for (int dt = 0; dt < 16; ++dt) {
        int col = ob + dt * 8 + tq * 2;
        float2 bv = *(const float2*)(bias + col);
        *(float2*)(rowA + col) = make_float2(acc[dt][0] + bv.x, acc[dt][1] + bv.y);
        *(float2*)(rowB + col) = make_float2(acc[dt][2] + bv.x, acc[dt][3] + bv.y);
    }
}

// ===========================================================================
extern "C" void kernel_launch(void* const* d_in, const int* in_sizes, int n_in,
                              void* d_out, int out_size)
{
    (void)in_sizes; (void)n_in; (void)out_size;
    const float* values = (const float*)d_in[0];
    const float* keys   = (const float*)d_in[1];
    const float* query  = (const float*)d_in[2];
    const float* Wv     = (const float*)d_in[3];
    const float* Wk     = (const float*)d_in[4];
    const float* Wq     = (const float*)d_in[5];
    const float* Wout   = (const float*)d_in[6];
    const float* bout   = (const float*)d_in[7];
    float* out = (float*)d_out;

    __half *Qp, *Kp, *Vp, *AOh, *Wh;
    cudaGetSymbolAddress((void**)&Qp,  g_Qp);
    cudaGetSymbolAddress((void**)&Kp,  g_Kp);
    cudaGetSymbolAddress((void**)&Vp,  g_Vp);
    cudaGetSymbolAddress((void**)&AOh, g_AOh);
    cudaGetSymbolAddress((void**)&Wh,  g_Wh);

    cudaFuncSetAttribute(flash_mma,
                         cudaFuncAttributeMaxDynamicSharedMemorySize, FSMEM);
    cudaFuncSetAttribute(outproj_mma,
                         cudaFuncAttributeMaxDynamicSharedMemorySize, OPSM);

    convw_kernel<<<(ODIM * EMB) / 1024, 256>>>(Wout, Wh);

    proj3_mma<<<dim3((NBATCH * LSEQ * NHEAD) / 128, 3), 256>>>(
        values, Wv, Vp, keys, Wk, Kp, query, Wq, Qp);

    flash_mma<<<dim3(LSEQ / 128, NBATCH * NHEAD), 256, FSMEM>>>(
        Qp, Kp, Vp, AOh);

    outproj_mma<<<dim3(ODIM / 128, (NBATCH * LSEQ) / 128), 256, OPSM>>>(
        AOh, Wh, bout, out);
}

// round 16
// speedup vs baseline: 1.4555x; 1.4555x over previous
#include <cuda_runtime.h>
#include <cuda_fp16.h>
#include <cstdint>

#define NBATCH 2
#define LSEQ   2048
#define EMB    1024
#define NHEAD  16
#define HD     64
#define ODIM   1024

__device__ __half g_Qp[NBATCH * LSEQ * EMB];
__device__ __half g_Kp[NBATCH * LSEQ * EMB];
__device__ __half g_Vp[NBATCH * LSEQ * EMB];
__device__ __half g_AOh[NBATCH * LSEQ * EMB];
__device__ __half g_Wh[ODIM * EMB];

__device__ __forceinline__ uint32_t smem_u32(const void* p) {
    uint32_t a;
    asm("{ .reg .u64 t; cvta.to.shared.u64 t, %1; cvt.u32.u64 %0, t; }"
        : "=r"(a) : "l"(p));
    return a;
}
__device__ __forceinline__ void mma16(float* c, const uint32_t* a,
                                      uint32_t b0, uint32_t b1) {
    asm volatile(
        "mma.sync.aligned.m16n8k16.row.col.f32.f16.f16.f32 "
        "{%0,%1,%2,%3}, {%4,%5,%6,%7}, {%8,%9}, {%0,%1,%2,%3};"
        : "+f"(c[0]), "+f"(c[1]), "+f"(c[2]), "+f"(c[3])
        : "r"(a[0]), "r"(a[1]), "r"(a[2]), "r"(a[3]), "r"(b0), "r"(b1));
}
#define LDSM4(r0, r1, r2, r3, addr) \
    asm volatile("ldmatrix.sync.aligned.m8n8.x4.shared.b16 {%0,%1,%2,%3}, [%4];" \
                 : "=r"(r0), "=r"(r1), "=r"(r2), "=r"(r3) : "r"(addr))
#define LDSM4T(r0, r1, r2, r3, addr) \
    asm volatile("ldmatrix.sync.aligned.m8n8.x4.trans.shared.b16 {%0,%1,%2,%3}, [%4];" \
                 : "=r"(r0), "=r"(r1), "=r"(r2), "=r"(r3) : "r"(addr))
#define CPA16(sm, gp) \
    asm volatile("cp.async.cg.shared.global [%0], [%1], 16;" :: "r"(sm), "l"(gp))
#define CPA_COMMIT() asm volatile("cp.async.commit_group;")
#define CPA_WAIT1()  asm volatile("cp.async.wait_group 1;")
#define CPA_WAIT0()  asm volatile("cp.async.wait_group 0;")

// exp(s/32), exp2 bit trick + degree-4 poly (rel err ~4e-5), FMA pipe only
__device__ __forceinline__ float fexp32(float s) {
    float y = s * 0.0450842200f;                 // (1/32)*log2(e)
    float z = y + 12582912.0f;
    int   e = __float_as_int(z) << 23;
    float f = y - (z - 12582912.0f);
    float r = 9.6181291e-3f;
    r = fmaf(r, f, 5.5504109e-2f);
    r = fmaf(r, f, 2.4022651e-1f);
    r = fmaf(r, f, 6.9314718e-1f);
    r = fmaf(r, f, 1.0f);
    return r * __int_as_float(e + 0x3f800000);
}

// ====== fused: per-head projections (HMMA) + Wout f16 convert ==============
// grid (512, 4): y in {0,1,2} -> V/K/Q projection; y==3 -> Wout convert.
__global__ __launch_bounds__(256) void proj3_mma(
    const float* __restrict__ Xv, const float* __restrict__ Wv, __half* __restrict__ Yv,
    const float* __restrict__ Xk, const float* __restrict__ Wk, __half* __restrict__ Yk,
    const float* __restrict__ Xq, const float* __restrict__ Wq, __half* __restrict__ Yq,
    const float* __restrict__ Wo, __half* __restrict__ Who)
{
    if (blockIdx.y == 3) {   // Wout -> f16: 512 blocks * 256 thr * 4 * 2 = 1M elems
        size_t i = ((size_t)blockIdx.x * 256 + threadIdx.x) * 4;
        const size_t stride = (size_t)512 * 256 * 4;
#pragma unroll
        for (int rep = 0; rep < 2; ++rep, i += stride) {
            float4 v = *(const float4*)(Wo + i);
            __half2 a = __floats2half2_rn(v.x, v.y);
            __half2 b = __floats2half2_rn(v.z, v.w);
            *(uint2*)(Who + i) = make_uint2(*(uint32_t*)&a, *(uint32_t*)&b);
        }
        return;
    }
    const float* X; const float* W; __half* Y;
    if (blockIdx.y == 0)      { X = Xv; W = Wv; Y = Yv; }
    else if (blockIdx.y == 1) { X = Xk; W = Wk; Y = Yk; }
    else                      { X = Xq; W = Wq; Y = Yq; }

    __shared__ __half Xs[128 * 64];
    __shared__ __half Ws[64 * 64];
    const int t = threadIdx.x, lane = t & 31, w = t >> 5;
    const int rb = blockIdx.x << 7;
    const uint32_t xsb = smem_u32(Xs), wsb = smem_u32(Ws);

#pragma unroll
    for (int p = 0; p < 4; ++p) {
        int idx = p * 256 + t, row = idx >> 3, ch = idx & 7;
        uint32_t so = (uint32_t)(row * 128 + ((ch ^ (row & 7)) << 4));
        size_t g = (size_t)(rb + row) * 64 + ch * 8;
        float4 a = *(const float4*)(X + g);
        float4 b = *(const float4*)(X + g + 4);
        __half2 h0 = __floats2half2_rn(a.x, a.y), h1 = __floats2half2_rn(a.z, a.w);
        __half2 h2 = __floats2half2_rn(b.x, b.y), h3 = __floats2half2_rn(b.z, b.w);
        *(uint4*)((char*)Xs + so) = make_uint4(*(uint32_t*)&h0, *(uint32_t*)&h1,
                                               *(uint32_t*)&h2, *(uint32_t*)&h3);
    }
#pragma unroll
    for (int p = 0; p < 2; ++p) {
        int idx = p * 256 + t, row = idx >> 3, ch = idx & 7;
        uint32_t so = (uint32_t)(row * 128 + ((ch ^ (row & 7)) << 4));
        size_t g = (size_t)row * 64 + ch * 8;
        float4 a = *(const float4*)(W + g);
        float4 b = *(const float4*)(W + g + 4);
        __half2 h0 = __floats2half2_rn(a.x, a.y), h1 = __floats2half2_rn(a.z, a.w);
        __half2 h2 = __floats2half2_rn(b.x, b.y), h3 = __floats2half2_rn(b.z, b.w);
        *(uint4*)((char*)Ws + so) = make_uint4(*(uint32_t*)&h0, *(uint32_t*)&h1,
                                               *(uint32_t*)&h2, *(uint32_t*)&h3);
    }
    __syncthreads();

    const int r0 = w * 16;
    float acc[8][4] = {};
#pragma unroll
    for (int kc = 0; kc < 4; ++kc) {
        int arow = r0 + ((lane >> 3) & 1) * 8 + (lane & 7);
        int ach  = kc * 2 + (lane >> 4);
        uint32_t aoff = (uint32_t)(arow * 128 + ((ach ^ (arow & 7)) << 4));
        uint32_t a[4];
        LDSM4(a[0], a[1], a[2], a[3], xsb + aoff);
#pragma unroll
        for (int jt2 = 0; jt2 < 4; ++jt2) {
            int wrow = jt2 * 16 + (lane >> 4) * 8 + (lane & 7);
            int wch  = kc * 2 + ((lane >> 3) & 1);
            uint32_t woff = (uint32_t)(wrow * 128 + ((wch ^ (wrow & 7)) << 4));
            uint32_t b0, b1, b2, b3;
            LDSM4(b0, b1, b2, b3, wsb + woff);
            mma16(acc[2 * jt2 + 0], a, b0, b1);
            mma16(acc[2 * jt2 + 1], a, b2, b3);
        }
    }

    const int g = lane >> 2, tq = lane & 3;
    __half* rowA = Y + (size_t)(rb + r0 + g) * 64;
    __half* rowB = Y + (size_t)(rb + r0 + g + 8) * 64;
#pragma unroll
    for (int dt = 0; dt < 8; ++dt) {
        int col = dt * 8 + tq * 2;
        *(__half2*)(rowA + col) = __floats2half2_rn(acc[dt][0], acc[dt][1]);
        *(__half2*)(rowB + col) = __floats2half2_rn(acc[dt][2], acc[dt][3]);
    }
}

// ============ flash attention (HMMA, 3-stage cp.async, 1 bar/tile) =========
#define QSTR 72
#define FST  18432                    // per stage: K(64*72*2) + V(64*72*2)
#define FQB  18432                    // Qs bytes
#define FSMEM (FQB + 3 * FST)         // 73728 bytes
__global__ __launch_bounds__(256) void flash_mma(
    const __half* __restrict__ Qp, const __half* __restrict__ Kp,
    const __half* __restrict__ Vp, __half* __restrict__ AOh)
{
    extern __shared__ char smb[];
    __half* Qs = (__half*)smb;
    const int t = threadIdx.x, lane = t & 31, w = t >> 5;
    const int nh = blockIdx.y;
    const int qb = blockIdx.x << 7;
    const size_t base = ((size_t)(nh >> 4) * LSEQ * NHEAD + (size_t)(nh & 15)) * HD;
    const uint32_t sbase = smem_u32(smb);
    const int lrow = t >> 3, lc8 = (t & 7) * 8;
    const uint32_t so0 = (uint32_t)((lrow * QSTR + lc8) * 2);
    const uint32_t so1 = (uint32_t)(((lrow + 32) * QSTR + lc8) * 2);

    // prologue: issue K/V stages 0 and 1
#pragma unroll
    for (int s = 0; s < 2; ++s) {
        const uint32_t sb = sbase + FQB + s * FST;
        const size_t g0 = base + (size_t)(s * 64 + lrow) * (NHEAD * HD) + lc8;
        const size_t g1 = base + (size_t)(s * 64 + lrow + 32) * (NHEAD * HD) + lc8;
        CPA16(sb + so0, Kp + g0);          CPA16(sb + so1, Kp + g1);
        CPA16(sb + 9216 + so0, Vp + g0);   CPA16(sb + 9216 + so1, Vp + g1);
        CPA_COMMIT();
    }
#pragma unroll
    for (int p = 0; p < 4; ++p) {
        int row = p * 32 + lrow;
        *(uint4*)(Qs + row * QSTR + lc8) =
            *(const uint4*)(Qp + base + (size_t)(qb + row) * (NHEAD * HD) + lc8);
    }
    __syncthreads();

    const int r0 = w * 16;
    uint32_t qa[4][4];
#pragma unroll
    for (int kc = 0; kc < 4; ++kc) {
        uint32_t addr = sbase + (uint32_t)((r0 + ((lane >> 3) & 1) * 8 + (lane & 7)) * (QSTR * 2)
                                           + kc * 32 + (lane >> 4) * 16);
        LDSM4(qa[kc][0], qa[kc][1], qa[kc][2], qa[kc][3], addr);
    }

    float oacc[8][4] = {};
    float lacc[4] = {};
    const uint32_t ONES = 0x3C003C00u;   // half2(1.0, 1.0)

    for (int kb = 0; kb < LSEQ / 64; ++kb) {
        if (kb < LSEQ / 64 - 1) CPA_WAIT1(); else CPA_WAIT0();
        __syncthreads();                  // stage kb ready for ALL warps

        if (kb + 2 < LSEQ / 64) {         // refill stage (kb+2)%3 (= freed (kb-1)%3)
            const uint32_t sb = sbase + FQB + ((kb + 2) % 3) * FST;
            const size_t g0 = base + (size_t)((kb + 2) * 64 + lrow) * (NHEAD * HD) + lc8;
            const size_t g1 = base + (size_t)((kb + 2) * 64 + lrow + 32) * (NHEAD * HD) + lc8;
            CPA16(sb + so0, Kp + g0);          CPA16(sb + so1, Kp + g1);
            CPA16(sb + 9216 + so0, Vp + g0);   CPA16(sb + 9216 + so1, Vp + g1);
            CPA_COMMIT();
        }

        const uint32_t ksb = sbase + FQB + (kb % 3) * FST;
        const uint32_t vsb = ksb + 9216;

        float sacc[8][4] = {};
#pragma unroll
        for (int kc = 0; kc < 4; ++kc) {
#pragma unroll
            for (int jt2 = 0; jt2 < 4; ++jt2) {
                uint32_t b0, b1, b2, b3;
                uint32_t addr = ksb + (uint32_t)((jt2 * 16 + (lane >> 4) * 8 + (lane & 7)) * (QSTR * 2)
                                                 + kc * 32 + ((lane >> 3) & 1) * 16);
                LDSM4(b0, b1, b2, b3, addr);
                mma16(sacc[2 * jt2 + 0], qa[kc], b0, b1);
                mma16(sacc[2 * jt2 + 1], qa[kc], b2, b3);
            }
        }

        uint32_t pa[4][4];
#pragma unroll
        for (int jt = 0; jt < 8; ++jt) {
            float p0 = fexp32(sacc[jt][0]);
            float p1 = fexp32(sacc[jt][1]);
            float p2 = fexp32(sacc[jt][2]);
            float p3 = fexp32(sacc[jt][3]);
            __half2 h01 = __floats2half2_rn(p0, p1);
            __half2 h23 = __floats2half2_rn(p2, p3);
            pa[jt >> 1][(jt & 1) * 2 + 0] = *(uint32_t*)&h01;
            pa[jt >> 1][(jt & 1) * 2 + 1] = *(uint32_t*)&h23;
        }

#pragma unroll
        for (int jc = 0; jc < 4; ++jc) {
            mma16(lacc, pa[jc], ONES, ONES);   // lsum += P @ 1
#pragma unroll
            for (int dt2 = 0; dt2 < 4; ++dt2) {
                uint32_t b0, b1, b2, b3;
                uint32_t addr = vsb + (uint32_t)((jc * 16 + ((lane >> 3) & 1) * 8 + (lane & 7)) * (QSTR * 2)
                                                 + dt2 * 32 + (lane >> 4) * 16);
                LDSM4T(b0, b1, b2, b3, addr);
                mma16(oacc[2 * dt2 + 0], pa[jc], b0, b1);
                mma16(oacc[2 * dt2 + 1], pa[jc], b2, b3);
            }
        }
    }

    const float inv0 = 1.0f / lacc[0], inv1 = 1.0f / lacc[2];
    const int g = lane >> 2, tq = lane & 3;
    __half* rowA = AOh + base + (size_t)(qb + r0 + g) * (NHEAD * HD);
    __half* rowB = AOh + base + (size_t)(qb + r0 + g + 8) * (NHEAD * HD);
#pragma unroll
    for (int dt = 0; dt < 8; ++dt) {
        int col = dt * 8 + tq * 2;
        *(__half2*)(rowA + col) = __floats2half2_rn(oacc[dt][0] * inv0, oacc[dt][1] * inv0);
        *(__half2*)(rowB + col) = __floats2half2_rn(oacc[dt][2] * inv1, oacc[dt][3] * inv1);
    }
}

// =============== output projection (HMMA f16, 128x128 tiles) ===============
#define OPA 0
#define OPW 16384
#define OPST 32768
#define OPSM (2 * OPST)   // 65536 bytes
__global__ __launch_bounds__(256, 2) void outproj_mma(
    const __half* __restrict__ Ah_g, const __half* __restrict__ Wh_g,
    const float* __restrict__ bias, float* __restrict__ Y)
{
    extern __shared__ char smb[];
    const int t = threadIdx.x, lane = t & 31, w = t >> 5;
    const int ob = blockIdx.x << 7, rb = blockIdx.y << 7;
    const uint32_t sb = smem_u32(smb);
    const int r0 = w * 16;
    float acc[16][4] = {};
    const int lrow = t >> 3, lch = t & 7;

    {   // prologue: stage 0
#pragma unroll
        for (int p = 0; p < 4; ++p) {
            int row = lrow + p * 32;
            uint32_t so = (uint32_t)(row * 128 + ((lch ^ (row & 7)) << 4));
            CPA16(sb + OPA + so, Ah_g + (size_t)(rb + row) * EMB + lch * 8);
            CPA16(sb + OPW + so, Wh_g + (size_t)(ob + row) * EMB + lch * 8);
        }
        CPA_COMMIT();
    }

    for (int ki = 0; ki < EMB / 64; ++ki) {
        const uint32_t st = (uint32_t)(ki & 1) * OPST;
        if (ki < EMB / 64 - 1) {
            const uint32_t sn = (uint32_t)((ki + 1) & 1) * OPST;
            const int kk = (ki + 1) * 64;
#pragma unroll
            for (int p = 0; p < 4; ++p) {
                int row = lrow + p * 32;
                uint32_t so = (uint32_t)(row * 128 + ((lch ^ (row & 7)) << 4));
                CPA16(sb + sn + OPA + so, Ah_g + (size_t)(rb + row) * EMB + kk + lch * 8);
                CPA16(sb + sn + OPW + so, Wh_g + (size_t)(ob + row) * EMB + kk + lch * 8);
            }
            CPA_COMMIT();
            CPA_WAIT1();
        } else {
            CPA_WAIT0();
        }
        __syncthreads();

#pragma unroll
        for (int kc = 0; kc < 4; ++kc) {
            int arow = r0 + ((lane >> 3) & 1) * 8 + (lane & 7);
            int ach  = kc * 2 + (lane >> 4);
            uint32_t aoff = (uint32_t)(arow * 128 + ((ach ^ (arow & 7)) << 4));
            uint32_t a[4];
            LDSM4(a[0], a[1], a[2], a[3], sb + st + OPA + aoff);
#pragma unroll
            for (int jt2 = 0; jt2 < 8; ++jt2) {
                int wrow = jt2 * 16 + (lane >> 4) * 8 + (lane & 7);
                int wch  = kc * 2 + ((lane >> 3) & 1);
                uint32_t woff = (uint32_t)(wrow * 128 + ((wch ^ (wrow & 7)) << 4));
                uint32_t b0, b1, b2, b3;
                LDSM4(b0, b1, b2, b3, sb + st + OPW + woff);
                mma16(acc[2 * jt2 + 0], a, b0, b1);
                mma16(acc[2 * jt2 + 1], a, b2, b3);
            }
        }
        __syncthreads();
    }

    const int g = lane >> 2, tq = lane & 3;
    float* rowA = Y + (size_t)(rb + r0 + g) * ODIM;
    float* rowB = Y + (size_t)(rb + r0 + g + 8) * ODIM;
#pragma unroll
    for (int dt = 0; dt < 16; ++dt) {
        int col = ob + dt * 8 + tq * 2;
        float2 bv = *(const float2*)(bias + col);
        *(float2*)(rowA + col) = make_float2(acc[dt][0] + bv.x, acc[dt][1] + bv.y);
        *(float2*)(rowB + col) = make_float2(acc[dt][2] + bv.x, acc[dt][3] + bv.y);
    }
}

// ===========================================================================
extern "C" void kernel_launch(void* const* d_in, const int* in_sizes, int n_in,
                              void* d_out, int out_size)
{
    (void)in_sizes; (void)n_in; (void)out_size;
    const float* values = (const float*)d_in[0];
    const float* keys   = (const float*)d_in[1];
    const float* query  = (const float*)d_in[2];
    const float* Wv     = (const float*)d_in[3];
    const float* Wk     = (const float*)d_in[4];
    const float* Wq     = (const float*)d_in[5];
    const float* Wout   = (const float*)d_in[6];
    const float* bout   = (const float*)d_in[7];
    float* out = (float*)d_out;

    __half *Qp, *Kp, *Vp, *AOh, *Wh;
    cudaGetSymbolAddress((void**)&Qp,  g_Qp);
    cudaGetSymbolAddress((void**)&Kp,  g_Kp);
    cudaGetSymbolAddress((void**)&Vp,  g_Vp);
    cudaGetSymbolAddress((void**)&AOh, g_AOh);
    cudaGetSymbolAddress((void**)&Wh,  g_Wh);

    cudaFuncSetAttribute(flash_mma,
                         cudaFuncAttributeMaxDynamicSharedMemorySize, FSMEM);
    cudaFuncSetAttribute(outproj_mma,
                         cudaFuncAttributeMaxDynamicSharedMemorySize, OPSM);

    proj3_mma<<<dim3((NBATCH * LSEQ * NHEAD) / 128, 4), 256>>>(
        values, Wv, Vp, keys, Wk, Kp, query, Wq, Qp, Wout, Wh);

    flash_mma<<<dim3(LSEQ / 128, NBATCH * NHEAD), 256, FSMEM>>>(
        Qp, Kp, Vp, AOh);

    outproj_mma<<<dim3(ODIM / 128, (NBATCH * LSEQ) / 128), 256, OPSM>>>(
        AOh, Wh, bout, out);
}